// round 6
// baseline (speedup 1.0000x reference)
#include <cuda_runtime.h>
#include <cuda_fp16.h>

#define NN 100000
#define NE 1600000
#define NG 512
#define NOUT 10
#define NB_SCAN ((NN + 1023) / 1024)

// GEMM geometry
#define SA_A 40                         // A smem row stride (halves), conflict-free
#define SA_W 136                        // W smem row stride (halves)
#define A_STAGE (128 * SA_A)            // halves per A buffer (hi or lo)
#define W_STAGE (32 * SA_W)
#define STAGE_HALVES (2 * A_STAGE + 2 * W_STAGE)
#define SMEM_BYTES (2 * STAGE_HALVES * 2)

// ---------------- scratch (device globals; no allocation allowed) ----------
__device__ __align__(16) __half g_gh[(size_t)NN * 128];   // g = dinv*(h@W), fp16
__device__ __align__(16) __half g_ah[(size_t)NN * 128];   // activation hi half
__device__ __align__(16) __half g_al[(size_t)NN * 128];   // activation lo half
__device__ __align__(16) __half g_wh[4 * 128 * 128];      // weights hi (4 layers)
__device__ __align__(16) __half g_wl[4 * 128 * 128];      // weights lo
__device__ __align__(16) int    g_deg[NN];
__device__ __align__(16) int    g_fill[NN];
__device__ __align__(16) int    g_off[NN + 1];
__device__ __align__(16) int    g_partial[NN];
__device__ __align__(16) int    g_bsums[128];
__device__ __align__(16) int    g_csr[NE];

// ---------------- helpers ----------------------------------------------------
__device__ __forceinline__ void split2(float a, float b, unsigned& hi, unsigned& lo) {
    __half h0 = __float2half_rn(a), h1 = __float2half_rn(b);
    __half l0 = __float2half_rn(a - __half2float(h0));
    __half l1 = __float2half_rn(b - __half2float(h1));
    __half2 H = __halves2half2(h0, h1), L = __halves2half2(l0, l1);
    hi = *(unsigned*)&H; lo = *(unsigned*)&L;
}

__device__ __forceinline__ void mma16816(float* c, const unsigned* a, const unsigned* b) {
    asm volatile(
        "mma.sync.aligned.m16n8k16.row.col.f32.f16.f16.f32 "
        "{%0,%1,%2,%3}, {%4,%5,%6,%7}, {%8,%9}, {%0,%1,%2,%3};"
        : "+f"(c[0]), "+f"(c[1]), "+f"(c[2]), "+f"(c[3])
        : "r"(a[0]), "r"(a[1]), "r"(a[2]), "r"(a[3]), "r"(b[0]), "r"(b[1]));
}

__device__ __forceinline__ void cpa16(__half* dst_smem, const __half* src) {
    unsigned d = (unsigned)__cvta_generic_to_shared(dst_smem);
    asm volatile("cp.async.cg.shared.global [%0], [%1], 16;" :: "r"(d), "l"(src));
}

// ---------------- prologue: degree, CSR build --------------------------------
__global__ void k_zero() {
    int i = blockIdx.x * blockDim.x + threadIdx.x;
    if (i < NN) { g_deg[i] = 0; g_fill[i] = 0; }
}

__global__ void k_edge_prep(const int* __restrict__ ei) {
    int t = blockIdx.x * blockDim.x + threadIdx.x;
    if (t < NE / 4) {
        int4 d = ((const int4*)(ei + NE))[t];
        atomicAdd(&g_deg[d.x], 1);
        atomicAdd(&g_deg[d.y], 1);
        atomicAdd(&g_deg[d.z], 1);
        atomicAdd(&g_deg[d.w], 1);
    }
}

// split x (blocks [0,12500)) and the 4 weight matrices (blocks >= 12500)
__global__ void k_split(const float* __restrict__ x,
                        const float* __restrict__ W_in,
                        const float* __restrict__ W_hid) {
    size_t i = (size_t)blockIdx.x * 256 + threadIdx.x;   // float4 index
    if (blockIdx.x < 12500) {
        float4 v = ((const float4*)x)[i];
        uint2 hi, lo;
        split2(v.x, v.y, hi.x, lo.x);
        split2(v.z, v.w, hi.y, lo.y);
        *(uint2*)(g_ah + i * 4) = hi;
        *(uint2*)(g_al + i * 4) = lo;
    } else {
        size_t wi = i - (size_t)12500 * 256;             // float4 idx, 16384 total
        if (wi < 16384) {
            float4 v = (wi < 4096) ? ((const float4*)W_in)[wi]
                                   : ((const float4*)W_hid)[wi - 4096];
            uint2 hi, lo;
            split2(v.x, v.y, hi.x, lo.x);
            split2(v.z, v.w, hi.y, lo.y);
            *(uint2*)(g_wh + wi * 4) = hi;
            *(uint2*)(g_wl + wi * 4) = lo;
        }
    }
}

__global__ void k_scan1() {
    __shared__ int sm[1024];
    int i = blockIdx.x * 1024 + threadIdx.x;
    int v = (i < NN) ? g_deg[i] : 0;
    sm[threadIdx.x] = v;
    __syncthreads();
    for (int d = 1; d < 1024; d <<= 1) {
        int t = (threadIdx.x >= d) ? sm[threadIdx.x - d] : 0;
        __syncthreads();
        sm[threadIdx.x] += t;
        __syncthreads();
    }
    if (i < NN) g_partial[i] = sm[threadIdx.x];
    if (threadIdx.x == 1023) g_bsums[blockIdx.x] = sm[1023];
}

__global__ void k_scan2(int nb) {
    __shared__ int sm[128];
    int v = (threadIdx.x < nb) ? g_bsums[threadIdx.x] : 0;
    sm[threadIdx.x] = v;
    __syncthreads();
    for (int d = 1; d < 128; d <<= 1) {
        int t = (threadIdx.x >= d) ? sm[threadIdx.x - d] : 0;
        __syncthreads();
        sm[threadIdx.x] += t;
        __syncthreads();
    }
    if (threadIdx.x < nb) g_bsums[threadIdx.x] = sm[threadIdx.x] - v;  // exclusive
}

__global__ void k_scan3() {
    int i = blockIdx.x * blockDim.x + threadIdx.x;
    if (i < NN) g_off[i + 1] = g_partial[i] + g_bsums[i >> 10];
    if (i == 0) g_off[0] = 0;
}

__global__ void k_fill(const int* __restrict__ ei) {
    int t = blockIdx.x * blockDim.x + threadIdx.x;
    if (t < NE / 4) {
        int4 s = ((const int4*)ei)[t];
        int4 d = ((const int4*)(ei + NE))[t];
        int p;
        p = g_off[d.x] + atomicAdd(&g_fill[d.x], 1); g_csr[p] = s.x;
        p = g_off[d.y] + atomicAdd(&g_fill[d.y], 1); g_csr[p] = s.y;
        p = g_off[d.z] + atomicAdd(&g_fill[d.z], 1); g_csr[p] = s.z;
        p = g_off[d.w] + atomicAdd(&g_fill[d.w], 1); g_csr[p] = s.w;
    }
}

// ---------------- tensor-core GEMM: g = fp16( dinv * (A @ W) ) ---------------
// A = (g_ah + g_al) split fp16, W = (g_wh + g_wl)[layer].  3-term split MMA.
// C[128,128]/CTA, 8 warps 2x4, warp tile 64x32.  K chunks of 32, 2-stage cp.async.
__global__ void __launch_bounds__(256, 2) k_gemm_tc(int layer) {
    extern __shared__ __half smh[];
    const __half* Wbh = g_wh + (size_t)layer * 16384;
    const __half* Wbl = g_wl + (size_t)layer * 16384;
    const int tid = threadIdx.x;
    const int row0 = blockIdx.x * 128;

    // stage pointers
    __half* Ah[2]; __half* Al[2]; __half* Wh[2]; __half* Wl[2];
#pragma unroll
    for (int s = 0; s < 2; s++) {
        __half* base = smh + s * STAGE_HALVES;
        Ah[s] = base;
        Al[s] = base + A_STAGE;
        Wh[s] = base + 2 * A_STAGE;
        Wl[s] = base + 2 * A_STAGE + W_STAGE;
    }

    // prefetch chunk c into stage s
    auto prefetch = [&](int c, int s) {
        const int k0 = c * 32;
#pragma unroll
        for (int o = tid; o < 512; o += 256) {           // A: 128 rows x 4 segs
            int r = o >> 2, seg = (o & 3) * 8;
            int grow = row0 + r;
            if (grow < NN) {
                cpa16(Ah[s] + r * SA_A + seg, g_ah + (size_t)grow * 128 + k0 + seg);
                cpa16(Al[s] + r * SA_A + seg, g_al + (size_t)grow * 128 + k0 + seg);
            }
        }
#pragma unroll
        for (int o = tid; o < 512; o += 256) {           // W: 32 rows x 16 segs
            int kr = o >> 4, seg = (o & 15) * 8;
            cpa16(Wh[s] + kr * SA_W + seg, Wbh + (size_t)(k0 + kr) * 128 + seg);
            cpa16(Wl[s] + kr * SA_W + seg, Wbl + (size_t)(k0 + kr) * 128 + seg);
        }
        asm volatile("cp.async.commit_group;");
    };

    const int lane = tid & 31, wid = tid >> 5;
    const int wm = wid >> 2, wn = wid & 3;
    const int g = lane >> 2, t2 = (lane & 3) << 1;

    float acc[4][4][4];
#pragma unroll
    for (int mt = 0; mt < 4; mt++)
#pragma unroll
        for (int nt = 0; nt < 4; nt++)
#pragma unroll
            for (int q = 0; q < 4; q++) acc[mt][nt][q] = 0.f;

    prefetch(0, 0);
    prefetch(1, 1);

#pragma unroll
    for (int c = 0; c < 4; c++) {
        const int s = c & 1;
        if (c < 3) asm volatile("cp.async.wait_group 1;");
        else       asm volatile("cp.async.wait_group 0;");
        __syncthreads();

#pragma unroll
        for (int ks = 0; ks < 2; ks++) {
            const int kc = ks * 16;
            // W fragments (ldmatrix.trans)
            unsigned bh[4][2], bl[4][2];
            const int krow = kc + (lane & 15);
#pragma unroll
            for (int nt = 0; nt < 4; nt++) {
                const int n0 = wn * 32 + nt * 8;
                unsigned sa = (unsigned)__cvta_generic_to_shared(Wh[s] + krow * SA_W + n0);
                asm volatile("ldmatrix.sync.aligned.m8n8.x2.trans.shared.b16 {%0,%1}, [%2];"
                             : "=r"(bh[nt][0]), "=r"(bh[nt][1]) : "r"(sa));
                unsigned sb = (unsigned)__cvta_generic_to_shared(Wl[s] + krow * SA_W + n0);
                asm volatile("ldmatrix.sync.aligned.m8n8.x2.trans.shared.b16 {%0,%1}, [%2];"
                             : "=r"(bl[nt][0]), "=r"(bl[nt][1]) : "r"(sb));
            }
            // A fragments per mt, then MMAs
#pragma unroll
            for (int mt = 0; mt < 4; mt++) {
                const __half* pa = Ah[s] + (wm * 64 + mt * 16 + g) * SA_A + kc + t2;
                const __half* pl = Al[s] + (wm * 64 + mt * 16 + g) * SA_A + kc + t2;
                unsigned ah_[4], al_[4];
                ah_[0] = *(const unsigned*)(pa);
                ah_[1] = *(const unsigned*)(pa + 8 * SA_A);
                ah_[2] = *(const unsigned*)(pa + 8);
                ah_[3] = *(const unsigned*)(pa + 8 * SA_A + 8);
                al_[0] = *(const unsigned*)(pl);
                al_[1] = *(const unsigned*)(pl + 8 * SA_A);
                al_[2] = *(const unsigned*)(pl + 8);
                al_[3] = *(const unsigned*)(pl + 8 * SA_A + 8);
#pragma unroll
                for (int nt = 0; nt < 4; nt++) {
                    mma16816(acc[mt][nt], ah_, bh[nt]);   // Ah @ Wh
                    mma16816(acc[mt][nt], ah_, bl[nt]);   // Ah @ Wl
                    mma16816(acc[mt][nt], al_, bh[nt]);   // Al @ Wh
                }
            }
        }
        __syncthreads();
        if (c + 2 < 4) prefetch(c + 2, s);
    }

    // epilogue: scale by dinv (from deg), pack fp16, store
#pragma unroll
    for (int mt = 0; mt < 4; mt++) {
        int r0 = row0 + wm * 64 + mt * 16 + g;
        int r1 = r0 + 8;
        float d0 = (r0 < NN) ? rsqrtf((float)(g_deg[r0] + 1)) : 0.f;
        float d1 = (r1 < NN) ? rsqrtf((float)(g_deg[r1] + 1)) : 0.f;
#pragma unroll
        for (int nt = 0; nt < 4; nt++) {
            int n = wn * 32 + nt * 8 + t2;
            if (r0 < NN) {
                __half2 p = __floats2half2_rn(acc[mt][nt][0] * d0, acc[mt][nt][1] * d0);
                *(__half2*)(g_gh + (size_t)r0 * 128 + n) = p;
            }
            if (r1 < NN) {
                __half2 p = __floats2half2_rn(acc[mt][nt][2] * d1, acc[mt][nt][3] * d1);
                *(__half2*)(g_gh + (size_t)r1 * 128 + n) = p;
            }
        }
    }
}

// ---------------- aggregation (gather CSR; writes split activations) --------
__global__ void __launch_bounds__(256) k_agg(const float* __restrict__ bias) {
    int n = (blockIdx.x * blockDim.x + threadIdx.x) >> 5;
    int lane = threadIdx.x & 31;
    if (n >= NN) return;
    const uint2* gb = (const uint2*)g_gh;       // 8B units; row stride = 32
    uint2 sv = gb[(size_t)n * 32 + lane];       // self-loop term
    __half2 h0 = *(__half2*)&sv.x, h1 = *(__half2*)&sv.y;
    float2 f0 = __half22float2(h0), f1 = __half22float2(h1);
    float4 acc = make_float4(f0.x, f0.y, f1.x, f1.y);

    int s = g_off[n], e = g_off[n + 1];
    for (int base = s; base < e; base += 32) {
        int cnt = e - base; if (cnt > 32) cnt = 32;
        int id = (lane < cnt) ? g_csr[base + lane] : 0;
        int jmax = cnt & ~1;
        for (int j = 0; j < jmax; j += 2) {
            int sa = __shfl_sync(0xffffffffu, id, j);
            int sb = __shfl_sync(0xffffffffu, id, j + 1);
            uint2 va = gb[(size_t)sa * 32 + lane];
            uint2 vb = gb[(size_t)sb * 32 + lane];
            __half2 s0 = __hadd2(*(__half2*)&va.x, *(__half2*)&vb.x);
            __half2 s1 = __hadd2(*(__half2*)&va.y, *(__half2*)&vb.y);
            float2 g0 = __half22float2(s0), g1 = __half22float2(s1);
            acc.x += g0.x; acc.y += g0.y; acc.z += g1.x; acc.w += g1.y;
        }
        if (cnt & 1) {
            int sa = __shfl_sync(0xffffffffu, id, cnt - 1);
            uint2 va = gb[(size_t)sa * 32 + lane];
            float2 g0 = __half22float2(*(__half2*)&va.x);
            float2 g1 = __half22float2(*(__half2*)&va.y);
            acc.x += g0.x; acc.y += g0.y; acc.z += g1.x; acc.w += g1.y;
        }
    }
    float dn = rsqrtf((float)(g_deg[n] + 1));
    float4 bb = *(const float4*)(bias + lane * 4);
    float4 o = make_float4(acc.x * dn + bb.x, acc.y * dn + bb.y,
                           acc.z * dn + bb.z, acc.w * dn + bb.w);
    uint2 hi, lo;
    split2(o.x, o.y, hi.x, lo.x);
    split2(o.z, o.w, hi.y, lo.y);
    *(uint2*)(g_ah + (size_t)n * 128 + lane * 4) = hi;
    *(uint2*)(g_al + (size_t)n * 128 + lane * 4) = lo;
}

// ---------------- mean pool per graph + output head -------------------------
__global__ void __launch_bounds__(128) k_pool(const int* __restrict__ batch,
                                              const float* __restrict__ Wout,
                                              const float* __restrict__ bout,
                                              float* __restrict__ out) {
    int gid = blockIdx.x;
    int c = threadIdx.x;
    int lo = 0, hi = NN;
    while (lo < hi) { int m = (lo + hi) >> 1; if (batch[m] < gid) lo = m + 1; else hi = m; }
    int start = lo;
    hi = NN;
    while (lo < hi) { int m = (lo + hi) >> 1; if (batch[m] < gid + 1) lo = m + 1; else hi = m; }
    int end = lo;

    float s = 0.f;
    for (int r = start; r < end; r++)
        s += __half2float(g_ah[(size_t)r * 128 + c]) +
             __half2float(g_al[(size_t)r * 128 + c]);
    __shared__ float pooled[128];
    int cnt = end - start;
    pooled[c] = (cnt > 0) ? s / (float)cnt : 0.f;
    __syncthreads();
    if (c < NOUT) {
        float a = bout[c];
#pragma unroll 8
        for (int k = 0; k < 128; k++) a += pooled[k] * Wout[k * NOUT + c];
        out[gid * NOUT + c] = a;
    }
}

// ---------------- launch ----------------------------------------------------
extern "C" void kernel_launch(void* const* d_in, const int* in_sizes, int n_in,
                              void* d_out, int out_size) {
    const float* x      = (const float*)d_in[0];
    const int*   ei     = (const int*)d_in[1];     // int32 (JAX x64 disabled)
    const int*   batch  = (const int*)d_in[2];     // int32
    const float* W_in   = (const float*)d_in[3];
    const float* b_in   = (const float*)d_in[4];
    const float* W_hid  = (const float*)d_in[5];
    const float* b_hid  = (const float*)d_in[6];
    const float* W_out  = (const float*)d_in[7];
    const float* b_out  = (const float*)d_in[8];
    float* out = (float*)d_out;

    cudaFuncSetAttribute(k_gemm_tc, cudaFuncAttributeMaxDynamicSharedMemorySize,
                         SMEM_BYTES);

    const int gemm_blocks = (NN + 127) / 128;
    const int agg_blocks  = (NN * 32 + 255) / 256;

    // gemm0 kept as 4th launch (ncu capture slot)
    k_zero<<<(NN + 255) / 256, 256>>>();
    k_edge_prep<<<(NE / 4 + 255) / 256, 256>>>(ei);
    k_split<<<12500 + 64, 256>>>(x, W_in, W_hid);
    k_gemm_tc<<<gemm_blocks, 256, SMEM_BYTES>>>(0);          // <- profiled
    k_scan1<<<NB_SCAN, 1024>>>();
    k_scan2<<<1, 128>>>(NB_SCAN);
    k_scan3<<<(NN + 255) / 256, 256>>>();
    k_fill<<<(NE / 4 + 255) / 256, 256>>>(ei);

    k_agg<<<agg_blocks, 256>>>(b_in);
    for (int i = 0; i < 3; i++) {
        k_gemm_tc<<<gemm_blocks, 256, SMEM_BYTES>>>(i + 1);
        k_agg<<<agg_blocks, 256>>>(b_hid + (size_t)i * 128);
    }

    k_pool<<<NG, 128>>>(batch, W_out, b_out, out);
}

// round 7
// speedup vs baseline: 1.0136x; 1.0136x over previous
#include <cuda_runtime.h>
#include <cuda_fp16.h>

#define NN 100000
#define NE 1600000
#define NG 512
#define NOUT 10
#define NB_SCAN ((NN + 1023) / 1024)

// GEMM geometry
#define SA_A 40                         // A smem row stride (halves), conflict-free
#define SA_W 136                        // W smem row stride (halves)
#define A_STAGE (128 * SA_A)            // halves per A buffer (hi or lo)
#define W_STAGE (32 * SA_W)
#define STAGE_HALVES (2 * A_STAGE + 2 * W_STAGE)
#define SMEM_BYTES (2 * STAGE_HALVES * 2)

// ---------------- scratch (device globals; no allocation allowed) ----------
__device__ __align__(16) __half g_gh[(size_t)NN * 128];   // g = dinv*(h@W), fp16
__device__ __align__(16) __half g_ah[(size_t)NN * 128];   // activation hi half
__device__ __align__(16) __half g_al[(size_t)NN * 128];   // activation lo half
__device__ __align__(16) __half g_wh[4 * 128 * 128];      // weights hi (4 layers)
__device__ __align__(16) __half g_wl[4 * 128 * 128];      // weights lo
__device__ __align__(16) int    g_deg[NN];
__device__ __align__(16) int    g_fill[NN];
__device__ __align__(16) int    g_off[NN + 1];
__device__ __align__(16) int    g_partial[NN];
__device__ __align__(16) int    g_bsums[128];
__device__ __align__(16) int    g_csr[NE];

// ---------------- helpers ----------------------------------------------------
__device__ __forceinline__ void split2(float a, float b, unsigned& hi, unsigned& lo) {
    __half h0 = __float2half_rn(a), h1 = __float2half_rn(b);
    __half l0 = __float2half_rn(a - __half2float(h0));
    __half l1 = __float2half_rn(b - __half2float(h1));
    __half2 H = __halves2half2(h0, h1), L = __halves2half2(l0, l1);
    hi = *(unsigned*)&H; lo = *(unsigned*)&L;
}

__device__ __forceinline__ void mma16816(float* c, const unsigned* a, const unsigned* b) {
    asm volatile(
        "mma.sync.aligned.m16n8k16.row.col.f32.f16.f16.f32 "
        "{%0,%1,%2,%3}, {%4,%5,%6,%7}, {%8,%9}, {%0,%1,%2,%3};"
        : "+f"(c[0]), "+f"(c[1]), "+f"(c[2]), "+f"(c[3])
        : "r"(a[0]), "r"(a[1]), "r"(a[2]), "r"(a[3]), "r"(b[0]), "r"(b[1]));
}

__device__ __forceinline__ void cpa16(__half* dst_smem, const __half* src) {
    unsigned d = (unsigned)__cvta_generic_to_shared(dst_smem);
    asm volatile("cp.async.cg.shared.global [%0], [%1], 16;" :: "r"(d), "l"(src));
}

__device__ __forceinline__ void ldsm_x4(unsigned* r, const __half* p) {
    unsigned a = (unsigned)__cvta_generic_to_shared(p);
    asm volatile("ldmatrix.sync.aligned.m8n8.x4.shared.b16 {%0,%1,%2,%3}, [%4];"
                 : "=r"(r[0]), "=r"(r[1]), "=r"(r[2]), "=r"(r[3]) : "r"(a));
}

__device__ __forceinline__ void ldsm_x4t(unsigned* r, const __half* p) {
    unsigned a = (unsigned)__cvta_generic_to_shared(p);
    asm volatile("ldmatrix.sync.aligned.m8n8.x4.trans.shared.b16 {%0,%1,%2,%3}, [%4];"
                 : "=r"(r[0]), "=r"(r[1]), "=r"(r[2]), "=r"(r[3]) : "r"(a));
}

// ---------------- prologue: degree, CSR build --------------------------------
__global__ void k_zero() {
    int i = blockIdx.x * blockDim.x + threadIdx.x;
    if (i < NN) { g_deg[i] = 0; g_fill[i] = 0; }
}

__global__ void k_edge_prep(const int* __restrict__ ei) {
    int t = blockIdx.x * blockDim.x + threadIdx.x;
    if (t < NE / 4) {
        int4 d = ((const int4*)(ei + NE))[t];
        atomicAdd(&g_deg[d.x], 1);
        atomicAdd(&g_deg[d.y], 1);
        atomicAdd(&g_deg[d.z], 1);
        atomicAdd(&g_deg[d.w], 1);
    }
}

// split x (blocks [0,12500)) and the 4 weight matrices (blocks >= 12500)
__global__ void k_split(const float* __restrict__ x,
                        const float* __restrict__ W_in,
                        const float* __restrict__ W_hid) {
    size_t i = (size_t)blockIdx.x * 256 + threadIdx.x;   // float4 index
    if (blockIdx.x < 12500) {
        float4 v = ((const float4*)x)[i];
        uint2 hi, lo;
        split2(v.x, v.y, hi.x, lo.x);
        split2(v.z, v.w, hi.y, lo.y);
        *(uint2*)(g_ah + i * 4) = hi;
        *(uint2*)(g_al + i * 4) = lo;
    } else {
        size_t wi = i - (size_t)12500 * 256;             // float4 idx, 16384 total
        if (wi < 16384) {
            float4 v = (wi < 4096) ? ((const float4*)W_in)[wi]
                                   : ((const float4*)W_hid)[wi - 4096];
            uint2 hi, lo;
            split2(v.x, v.y, hi.x, lo.x);
            split2(v.z, v.w, hi.y, lo.y);
            *(uint2*)(g_wh + wi * 4) = hi;
            *(uint2*)(g_wl + wi * 4) = lo;
        }
    }
}

__global__ void k_scan1() {
    __shared__ int sm[1024];
    int i = blockIdx.x * 1024 + threadIdx.x;
    int v = (i < NN) ? g_deg[i] : 0;
    sm[threadIdx.x] = v;
    __syncthreads();
    for (int d = 1; d < 1024; d <<= 1) {
        int t = (threadIdx.x >= d) ? sm[threadIdx.x - d] : 0;
        __syncthreads();
        sm[threadIdx.x] += t;
        __syncthreads();
    }
    if (i < NN) g_partial[i] = sm[threadIdx.x];
    if (threadIdx.x == 1023) g_bsums[blockIdx.x] = sm[1023];
}

__global__ void k_scan2(int nb) {
    __shared__ int sm[128];
    int v = (threadIdx.x < nb) ? g_bsums[threadIdx.x] : 0;
    sm[threadIdx.x] = v;
    __syncthreads();
    for (int d = 1; d < 128; d <<= 1) {
        int t = (threadIdx.x >= d) ? sm[threadIdx.x - d] : 0;
        __syncthreads();
        sm[threadIdx.x] += t;
        __syncthreads();
    }
    if (threadIdx.x < nb) g_bsums[threadIdx.x] = sm[threadIdx.x] - v;  // exclusive
}

__global__ void k_scan3() {
    int i = blockIdx.x * blockDim.x + threadIdx.x;
    if (i < NN) g_off[i + 1] = g_partial[i] + g_bsums[i >> 10];
    if (i == 0) g_off[0] = 0;
}

__global__ void k_fill(const int* __restrict__ ei) {
    int t = blockIdx.x * blockDim.x + threadIdx.x;
    if (t < NE / 4) {
        int4 s = ((const int4*)ei)[t];
        int4 d = ((const int4*)(ei + NE))[t];
        int p;
        p = g_off[d.x] + atomicAdd(&g_fill[d.x], 1); g_csr[p] = s.x;
        p = g_off[d.y] + atomicAdd(&g_fill[d.y], 1); g_csr[p] = s.y;
        p = g_off[d.z] + atomicAdd(&g_fill[d.z], 1); g_csr[p] = s.z;
        p = g_off[d.w] + atomicAdd(&g_fill[d.w], 1); g_csr[p] = s.w;
    }
}

// ---------------- tensor-core GEMM: g = fp16( dinv * (A @ W) ) ---------------
// A = (g_ah + g_al) split fp16, W = (g_wh + g_wl)[layer].  3-term split MMA.
// C[128,128]/CTA, 8 warps 2x4, warp tile 64x32.  K chunks of 32, 2-stage cp.async.
// All smem fragment loads via ldmatrix.x4 (A) / ldmatrix.x4.trans (W).
__global__ void __launch_bounds__(256, 2) k_gemm_tc(int layer) {
    extern __shared__ __half smh[];
    const __half* Wbh = g_wh + (size_t)layer * 16384;
    const __half* Wbl = g_wl + (size_t)layer * 16384;
    const int tid = threadIdx.x;
    const int row0 = blockIdx.x * 128;

    __half* Ah[2]; __half* Al[2]; __half* Wh[2]; __half* Wl[2];
#pragma unroll
    for (int s = 0; s < 2; s++) {
        __half* base = smh + s * STAGE_HALVES;
        Ah[s] = base;
        Al[s] = base + A_STAGE;
        Wh[s] = base + 2 * A_STAGE;
        Wl[s] = base + 2 * A_STAGE + W_STAGE;
    }

    auto prefetch = [&](int c, int s) {
        const int k0 = c * 32;
#pragma unroll
        for (int o = tid; o < 512; o += 256) {           // A: 128 rows x 4 segs
            int r = o >> 2, seg = (o & 3) * 8;
            int grow = row0 + r;
            if (grow < NN) {
                cpa16(Ah[s] + r * SA_A + seg, g_ah + (size_t)grow * 128 + k0 + seg);
                cpa16(Al[s] + r * SA_A + seg, g_al + (size_t)grow * 128 + k0 + seg);
            }
        }
#pragma unroll
        for (int o = tid; o < 512; o += 256) {           // W: 32 rows x 16 segs
            int kr = o >> 4, seg = (o & 15) * 8;
            cpa16(Wh[s] + kr * SA_W + seg, Wbh + (size_t)(k0 + kr) * 128 + seg);
            cpa16(Wl[s] + kr * SA_W + seg, Wbl + (size_t)(k0 + kr) * 128 + seg);
        }
        asm volatile("cp.async.commit_group;");
    };

    const int lane = tid & 31, wid = tid >> 5;
    const int wm = wid >> 2, wn = wid & 3;
    const int g = lane >> 2, t2 = (lane & 3) << 1;
    // ldmatrix.x4 (A, non-trans) lane addressing
    const int lr = lane & 7, sel = lane >> 3;
    const int a_row_off = (sel & 1) * 8;     // sel 1,3 -> rows +8
    const int a_col_off = (sel & 2) * 4;     // sel 2,3 -> cols +8
    // ldmatrix.x4.trans (W) lane addressing
    const int w_krow = lane & 15;            // k row within 16
    const int w_noff = (lane >> 4) * 8;      // lanes 16-31 -> n+8

    float acc[4][4][4];
#pragma unroll
    for (int mt = 0; mt < 4; mt++)
#pragma unroll
        for (int nt = 0; nt < 4; nt++)
#pragma unroll
            for (int q = 0; q < 4; q++) acc[mt][nt][q] = 0.f;

    prefetch(0, 0);
    prefetch(1, 1);

#pragma unroll
    for (int c = 0; c < 4; c++) {
        const int s = c & 1;
        if (c < 3) asm volatile("cp.async.wait_group 1;");
        else       asm volatile("cp.async.wait_group 0;");
        __syncthreads();

#pragma unroll
        for (int ks = 0; ks < 2; ks++) {
            const int kc = ks * 16;
            // W fragments: 2 x4.trans per split cover all 32 n-cols
            unsigned bh2[2][4], bl2[2][4];
#pragma unroll
            for (int nh = 0; nh < 2; nh++) {
                const __half* pw = Wh[s] + (kc + w_krow) * SA_W + wn * 32 + nh * 16 + w_noff;
                ldsm_x4t(bh2[nh], pw);
                const __half* pl = Wl[s] + (kc + w_krow) * SA_W + wn * 32 + nh * 16 + w_noff;
                ldsm_x4t(bl2[nh], pl);
            }
            // A fragments per mt (1 x4 per split), then MMAs
#pragma unroll
            for (int mt = 0; mt < 4; mt++) {
                const int m0 = wm * 64 + mt * 16;
                unsigned ah_[4], al_[4];
                ldsm_x4(ah_, Ah[s] + (m0 + lr + a_row_off) * SA_A + kc + a_col_off);
                ldsm_x4(al_, Al[s] + (m0 + lr + a_row_off) * SA_A + kc + a_col_off);
#pragma unroll
                for (int nt = 0; nt < 4; nt++) {
                    unsigned bhf[2] = {bh2[nt >> 1][(nt & 1) * 2],
                                       bh2[nt >> 1][(nt & 1) * 2 + 1]};
                    unsigned blf[2] = {bl2[nt >> 1][(nt & 1) * 2],
                                       bl2[nt >> 1][(nt & 1) * 2 + 1]};
                    mma16816(acc[mt][nt], ah_, bhf);   // Ah @ Wh
                    mma16816(acc[mt][nt], ah_, blf);   // Ah @ Wl
                    mma16816(acc[mt][nt], al_, bhf);   // Al @ Wh
                }
            }
        }
        __syncthreads();
        if (c + 2 < 4) prefetch(c + 2, s);
    }

    // epilogue: scale by dinv (from deg), pack fp16, store
#pragma unroll
    for (int mt = 0; mt < 4; mt++) {
        int r0 = row0 + wm * 64 + mt * 16 + g;
        int r1 = r0 + 8;
        float d0 = (r0 < NN) ? rsqrtf((float)(g_deg[r0] + 1)) : 0.f;
        float d1 = (r1 < NN) ? rsqrtf((float)(g_deg[r1] + 1)) : 0.f;
#pragma unroll
        for (int nt = 0; nt < 4; nt++) {
            int n = wn * 32 + nt * 8 + t2;
            if (r0 < NN) {
                __half2 p = __floats2half2_rn(acc[mt][nt][0] * d0, acc[mt][nt][1] * d0);
                *(__half2*)(g_gh + (size_t)r0 * 128 + n) = p;
            }
            if (r1 < NN) {
                __half2 p = __floats2half2_rn(acc[mt][nt][2] * d1, acc[mt][nt][3] * d1);
                *(__half2*)(g_gh + (size_t)r1 * 128 + n) = p;
            }
        }
    }
}

// ---------------- aggregation (gather CSR; writes split activations) --------
__global__ void __launch_bounds__(256) k_agg(const float* __restrict__ bias) {
    int n = (blockIdx.x * blockDim.x + threadIdx.x) >> 5;
    int lane = threadIdx.x & 31;
    if (n >= NN) return;
    const uint2* gb = (const uint2*)g_gh;       // 8B units; row stride = 32
    uint2 sv = gb[(size_t)n * 32 + lane];       // self-loop term
    __half2 h0 = *(__half2*)&sv.x, h1 = *(__half2*)&sv.y;
    float2 f0 = __half22float2(h0), f1 = __half22float2(h1);
    float4 acc = make_float4(f0.x, f0.y, f1.x, f1.y);

    int s = g_off[n], e = g_off[n + 1];
    for (int base = s; base < e; base += 32) {
        int cnt = e - base; if (cnt > 32) cnt = 32;
        int id = (lane < cnt) ? g_csr[base + lane] : 0;
        int jmax = cnt & ~1;
        for (int j = 0; j < jmax; j += 2) {
            int sa = __shfl_sync(0xffffffffu, id, j);
            int sb = __shfl_sync(0xffffffffu, id, j + 1);
            uint2 va = gb[(size_t)sa * 32 + lane];
            uint2 vb = gb[(size_t)sb * 32 + lane];
            __half2 s0 = __hadd2(*(__half2*)&va.x, *(__half2*)&vb.x);
            __half2 s1 = __hadd2(*(__half2*)&va.y, *(__half2*)&vb.y);
            float2 g0 = __half22float2(s0), g1 = __half22float2(s1);
            acc.x += g0.x; acc.y += g0.y; acc.z += g1.x; acc.w += g1.y;
        }
        if (cnt & 1) {
            int sa = __shfl_sync(0xffffffffu, id, cnt - 1);
            uint2 va = gb[(size_t)sa * 32 + lane];
            float2 g0 = __half22float2(*(__half2*)&va.x);
            float2 g1 = __half22float2(*(__half2*)&va.y);
            acc.x += g0.x; acc.y += g0.y; acc.z += g1.x; acc.w += g1.y;
        }
    }
    float dn = rsqrtf((float)(g_deg[n] + 1));
    float4 bb = *(const float4*)(bias + lane * 4);
    float4 o = make_float4(acc.x * dn + bb.x, acc.y * dn + bb.y,
                           acc.z * dn + bb.z, acc.w * dn + bb.w);
    uint2 hi, lo;
    split2(o.x, o.y, hi.x, lo.x);
    split2(o.z, o.w, hi.y, lo.y);
    *(uint2*)(g_ah + (size_t)n * 128 + lane * 4) = hi;
    *(uint2*)(g_al + (size_t)n * 128 + lane * 4) = lo;
}

// ---------------- mean pool per graph + output head -------------------------
__global__ void __launch_bounds__(128) k_pool(const int* __restrict__ batch,
                                              const float* __restrict__ Wout,
                                              const float* __restrict__ bout,
                                              float* __restrict__ out) {
    int gid = blockIdx.x;
    int c = threadIdx.x;
    int lo = 0, hi = NN;
    while (lo < hi) { int m = (lo + hi) >> 1; if (batch[m] < gid) lo = m + 1; else hi = m; }
    int start = lo;
    hi = NN;
    while (lo < hi) { int m = (lo + hi) >> 1; if (batch[m] < gid + 1) lo = m + 1; else hi = m; }
    int end = lo;

    float s = 0.f;
    for (int r = start; r < end; r++)
        s += __half2float(g_ah[(size_t)r * 128 + c]) +
             __half2float(g_al[(size_t)r * 128 + c]);
    __shared__ float pooled[128];
    int cnt = end - start;
    pooled[c] = (cnt > 0) ? s / (float)cnt : 0.f;
    __syncthreads();
    if (c < NOUT) {
        float a = bout[c];
#pragma unroll 8
        for (int k = 0; k < 128; k++) a += pooled[k] * Wout[k * NOUT + c];
        out[gid * NOUT + c] = a;
    }
}

// ---------------- launch ----------------------------------------------------
extern "C" void kernel_launch(void* const* d_in, const int* in_sizes, int n_in,
                              void* d_out, int out_size) {
    const float* x      = (const float*)d_in[0];
    const int*   ei     = (const int*)d_in[1];     // int32 (JAX x64 disabled)
    const int*   batch  = (const int*)d_in[2];     // int32
    const float* W_in   = (const float*)d_in[3];
    const float* b_in   = (const float*)d_in[4];
    const float* W_hid  = (const float*)d_in[5];
    const float* b_hid  = (const float*)d_in[6];
    const float* W_out  = (const float*)d_in[7];
    const float* b_out  = (const float*)d_in[8];
    float* out = (float*)d_out;

    cudaFuncSetAttribute(k_gemm_tc, cudaFuncAttributeMaxDynamicSharedMemorySize,
                         SMEM_BYTES);

    const int gemm_blocks = (NN + 127) / 128;
    const int agg_blocks  = (NN * 32 + 255) / 256;

    // gemm0 kept as 4th launch (ncu capture slot)
    k_zero<<<(NN + 255) / 256, 256>>>();
    k_edge_prep<<<(NE / 4 + 255) / 256, 256>>>(ei);
    k_split<<<12500 + 64, 256>>>(x, W_in, W_hid);
    k_gemm_tc<<<gemm_blocks, 256, SMEM_BYTES>>>(0);          // <- profiled
    k_scan1<<<NB_SCAN, 1024>>>();
    k_scan2<<<1, 128>>>(NB_SCAN);
    k_scan3<<<(NN + 255) / 256, 256>>>();
    k_fill<<<(NE / 4 + 255) / 256, 256>>>(ei);

    k_agg<<<agg_blocks, 256>>>(b_in);
    for (int i = 0; i < 3; i++) {
        k_gemm_tc<<<gemm_blocks, 256, SMEM_BYTES>>>(i + 1);
        k_agg<<<agg_blocks, 256>>>(b_hid + (size_t)i * 128);
    }

    k_pool<<<NG, 128>>>(batch, W_out, b_out, out);
}

// round 8
// speedup vs baseline: 1.0254x; 1.0116x over previous
#include <cuda_runtime.h>
#include <cuda_fp16.h>

#define NN 100000
#define NE 1600000
#define NG 512
#define NOUT 10
#define NB_SCAN ((NN + 1023) / 1024)

// GEMM geometry: CTA = 128x64 output, 8 warps (4x2), warp tile 32x32
#define SA_A 40                         // A smem row stride (halves)
#define SA_W 72                         // W smem row stride (halves)
#define A_STAGE (128 * SA_A)
#define W_STAGE (32 * SA_W)
#define STAGE_HALVES (2 * A_STAGE + 2 * W_STAGE)
#define SMEM_BYTES (2 * STAGE_HALVES * 2)   // 59392 B

// ---------------- scratch (device globals; no allocation allowed) ----------
__device__ __align__(16) __half g_gh[(size_t)NN * 128];   // g = dinv*(h@W), fp16
__device__ __align__(16) __half g_ah[(size_t)NN * 128];   // activation hi half
__device__ __align__(16) __half g_al[(size_t)NN * 128];   // activation lo half
__device__ __align__(16) __half g_wh[4 * 128 * 128];      // weights hi (4 layers)
__device__ __align__(16) __half g_wl[4 * 128 * 128];      // weights lo
__device__ __align__(16) int    g_deg[NN];
__device__ __align__(16) int    g_fill[NN];
__device__ __align__(16) int    g_off[NN + 1];
__device__ __align__(16) int    g_partial[NN];
__device__ __align__(16) int    g_bsums[128];
__device__ __align__(16) int    g_csr[NE];

// ---------------- helpers ----------------------------------------------------
__device__ __forceinline__ void split2(float a, float b, unsigned& hi, unsigned& lo) {
    __half h0 = __float2half_rn(a), h1 = __float2half_rn(b);
    __half l0 = __float2half_rn(a - __half2float(h0));
    __half l1 = __float2half_rn(b - __half2float(h1));
    __half2 H = __halves2half2(h0, h1), L = __halves2half2(l0, l1);
    hi = *(unsigned*)&H; lo = *(unsigned*)&L;
}

__device__ __forceinline__ void mma16816(float* c, const unsigned* a, const unsigned* b) {
    asm volatile(
        "mma.sync.aligned.m16n8k16.row.col.f32.f16.f16.f32 "
        "{%0,%1,%2,%3}, {%4,%5,%6,%7}, {%8,%9}, {%0,%1,%2,%3};"
        : "+f"(c[0]), "+f"(c[1]), "+f"(c[2]), "+f"(c[3])
        : "r"(a[0]), "r"(a[1]), "r"(a[2]), "r"(a[3]), "r"(b[0]), "r"(b[1]));
}

__device__ __forceinline__ void cpa16(__half* dst_smem, const __half* src) {
    unsigned d = (unsigned)__cvta_generic_to_shared(dst_smem);
    asm volatile("cp.async.cg.shared.global [%0], [%1], 16;" :: "r"(d), "l"(src));
}

__device__ __forceinline__ void ldsm_x4(unsigned* r, const __half* p) {
    unsigned a = (unsigned)__cvta_generic_to_shared(p);
    asm volatile("ldmatrix.sync.aligned.m8n8.x4.shared.b16 {%0,%1,%2,%3}, [%4];"
                 : "=r"(r[0]), "=r"(r[1]), "=r"(r[2]), "=r"(r[3]) : "r"(a));
}

__device__ __forceinline__ void ldsm_x4t(unsigned* r, const __half* p) {
    unsigned a = (unsigned)__cvta_generic_to_shared(p);
    asm volatile("ldmatrix.sync.aligned.m8n8.x4.trans.shared.b16 {%0,%1,%2,%3}, [%4];"
                 : "=r"(r[0]), "=r"(r[1]), "=r"(r[2]), "=r"(r[3]) : "r"(a));
}

// ---------------- prologue: degree, CSR build --------------------------------
__global__ void k_zero() {
    int i = blockIdx.x * blockDim.x + threadIdx.x;
    if (i < NN) g_deg[i] = 0;
}

__global__ void k_edge_prep(const int* __restrict__ ei) {
    int t = blockIdx.x * blockDim.x + threadIdx.x;
    if (t < NE / 4) {
        int4 d = ((const int4*)(ei + NE))[t];
        atomicAdd(&g_deg[d.x], 1);
        atomicAdd(&g_deg[d.y], 1);
        atomicAdd(&g_deg[d.z], 1);
        atomicAdd(&g_deg[d.w], 1);
    }
}

// split x (blocks [0,12500)) and the 4 weight matrices (blocks >= 12500)
__global__ void k_split(const float* __restrict__ x,
                        const float* __restrict__ W_in,
                        const float* __restrict__ W_hid) {
    size_t i = (size_t)blockIdx.x * 256 + threadIdx.x;   // float4 index
    if (blockIdx.x < 12500) {
        float4 v = ((const float4*)x)[i];
        uint2 hi, lo;
        split2(v.x, v.y, hi.x, lo.x);
        split2(v.z, v.w, hi.y, lo.y);
        *(uint2*)(g_ah + i * 4) = hi;
        *(uint2*)(g_al + i * 4) = lo;
    } else {
        size_t wi = i - (size_t)12500 * 256;             // float4 idx, 16384 total
        if (wi < 16384) {
            float4 v = (wi < 4096) ? ((const float4*)W_in)[wi]
                                   : ((const float4*)W_hid)[wi - 4096];
            uint2 hi, lo;
            split2(v.x, v.y, hi.x, lo.x);
            split2(v.z, v.w, hi.y, lo.y);
            *(uint2*)(g_wh + wi * 4) = hi;
            *(uint2*)(g_wl + wi * 4) = lo;
        }
    }
}

__global__ void k_scan1() {
    __shared__ int sm[1024];
    int i = blockIdx.x * 1024 + threadIdx.x;
    int v = (i < NN) ? g_deg[i] : 0;
    sm[threadIdx.x] = v;
    __syncthreads();
    for (int d = 1; d < 1024; d <<= 1) {
        int t = (threadIdx.x >= d) ? sm[threadIdx.x - d] : 0;
        __syncthreads();
        sm[threadIdx.x] += t;
        __syncthreads();
    }
    if (i < NN) g_partial[i] = sm[threadIdx.x];
    if (threadIdx.x == 1023) g_bsums[blockIdx.x] = sm[1023];
}

__global__ void k_scan2(int nb) {
    __shared__ int sm[128];
    int v = (threadIdx.x < nb) ? g_bsums[threadIdx.x] : 0;
    sm[threadIdx.x] = v;
    __syncthreads();
    for (int d = 1; d < 128; d <<= 1) {
        int t = (threadIdx.x >= d) ? sm[threadIdx.x - d] : 0;
        __syncthreads();
        sm[threadIdx.x] += t;
        __syncthreads();
    }
    if (threadIdx.x < nb) g_bsums[threadIdx.x] = sm[threadIdx.x] - v;  // exclusive
}

// offsets; also seed g_fill with the exclusive offset (fill uses it directly)
__global__ void k_scan3() {
    int i = blockIdx.x * blockDim.x + threadIdx.x;
    if (i < NN) {
        int excl = g_partial[i] + g_bsums[i >> 10] - g_deg[i];
        g_off[i] = excl;
        g_fill[i] = excl;
        if (i == NN - 1) g_off[NN] = g_partial[i] + g_bsums[i >> 10];
    }
}

__global__ void k_fill(const int* __restrict__ ei) {
    int t = blockIdx.x * blockDim.x + threadIdx.x;
    if (t < NE / 4) {
        int4 s = ((const int4*)ei)[t];
        int4 d = ((const int4*)(ei + NE))[t];
        int p;
        p = atomicAdd(&g_fill[d.x], 1); g_csr[p] = s.x;
        p = atomicAdd(&g_fill[d.y], 1); g_csr[p] = s.y;
        p = atomicAdd(&g_fill[d.z], 1); g_csr[p] = s.z;
        p = atomicAdd(&g_fill[d.w], 1); g_csr[p] = s.w;
    }
}

// ---------------- tensor-core GEMM: g = fp16( dinv * (A @ W) ) ---------------
// CTA = 128x64 output; grid = rowTiles*2 (blockIdx.x&1 selects col half).
// 8 warps 4x2, warp tile 32x32.  K chunks of 32, 2-stage cp.async. 3 CTAs/SM.
__global__ void __launch_bounds__(256, 3) k_gemm_tc(int layer) {
    extern __shared__ __half smh[];
    const int col0 = (blockIdx.x & 1) * 64;
    const int row0 = (blockIdx.x >> 1) * 128;
    const __half* Wbh = g_wh + (size_t)layer * 16384 + col0;
    const __half* Wbl = g_wl + (size_t)layer * 16384 + col0;
    const int tid = threadIdx.x;

    __half* Ah[2]; __half* Al[2]; __half* Wh[2]; __half* Wl[2];
#pragma unroll
    for (int s = 0; s < 2; s++) {
        __half* base = smh + s * STAGE_HALVES;
        Ah[s] = base;
        Al[s] = base + A_STAGE;
        Wh[s] = base + 2 * A_STAGE;
        Wl[s] = base + 2 * A_STAGE + W_STAGE;
    }

    auto prefetch = [&](int c, int s) {
        const int k0 = c * 32;
#pragma unroll
        for (int o = tid; o < 512; o += 256) {           // A: 128 rows x 4 segs
            int r = o >> 2, seg = (o & 3) * 8;
            int grow = row0 + r;
            if (grow < NN) {
                cpa16(Ah[s] + r * SA_A + seg, g_ah + (size_t)grow * 128 + k0 + seg);
                cpa16(Al[s] + r * SA_A + seg, g_al + (size_t)grow * 128 + k0 + seg);
            }
        }
        {                                                 // W: 32 rows x 8 segs
            int kr = tid >> 3, seg = (tid & 7) * 8;
            cpa16(Wh[s] + kr * SA_W + seg, Wbh + (size_t)(k0 + kr) * 128 + seg);
            cpa16(Wl[s] + kr * SA_W + seg, Wbl + (size_t)(k0 + kr) * 128 + seg);
        }
        asm volatile("cp.async.commit_group;");
    };

    const int lane = tid & 31, wid = tid >> 5;
    const int wm = wid >> 1, wn = wid & 1;               // 4x2 warp grid
    const int g = lane >> 2, t2 = (lane & 3) << 1;
    const int lr = lane & 7, sel = lane >> 3;
    const int a_row_off = (sel & 1) * 8;
    const int a_col_off = (sel & 2) * 4;
    const int w_krow = lane & 15;
    const int w_noff = (lane >> 4) * 8;

    float acc[2][4][4];
#pragma unroll
    for (int mt = 0; mt < 2; mt++)
#pragma unroll
        for (int nt = 0; nt < 4; nt++)
#pragma unroll
            for (int q = 0; q < 4; q++) acc[mt][nt][q] = 0.f;

    prefetch(0, 0);
    prefetch(1, 1);

#pragma unroll
    for (int c = 0; c < 4; c++) {
        const int s = c & 1;
        if (c < 3) asm volatile("cp.async.wait_group 1;");
        else       asm volatile("cp.async.wait_group 0;");
        __syncthreads();

#pragma unroll
        for (int ks = 0; ks < 2; ks++) {
            const int kc = ks * 16;
            // W fragments: 2 x4.trans per split cover the warp's 32 n-cols
            unsigned bh2[2][4], bl2[2][4];
#pragma unroll
            for (int nh = 0; nh < 2; nh++) {
                const __half* pw = Wh[s] + (kc + w_krow) * SA_W + wn * 32 + nh * 16 + w_noff;
                ldsm_x4t(bh2[nh], pw);
                const __half* pl = Wl[s] + (kc + w_krow) * SA_W + wn * 32 + nh * 16 + w_noff;
                ldsm_x4t(bl2[nh], pl);
            }
#pragma unroll
            for (int mt = 0; mt < 2; mt++) {
                const int m0 = wm * 32 + mt * 16;
                unsigned ah_[4], al_[4];
                ldsm_x4(ah_, Ah[s] + (m0 + lr + a_row_off) * SA_A + kc + a_col_off);
                ldsm_x4(al_, Al[s] + (m0 + lr + a_row_off) * SA_A + kc + a_col_off);
#pragma unroll
                for (int nt = 0; nt < 4; nt++) {
                    unsigned bhf[2] = {bh2[nt >> 1][(nt & 1) * 2],
                                       bh2[nt >> 1][(nt & 1) * 2 + 1]};
                    unsigned blf[2] = {bl2[nt >> 1][(nt & 1) * 2],
                                       bl2[nt >> 1][(nt & 1) * 2 + 1]};
                    mma16816(acc[mt][nt], ah_, bhf);   // Ah @ Wh
                    mma16816(acc[mt][nt], ah_, blf);   // Ah @ Wl
                    mma16816(acc[mt][nt], al_, bhf);   // Al @ Wh
                }
            }
        }
        __syncthreads();
        if (c + 2 < 4) prefetch(c + 2, s);
    }

    // epilogue: scale by dinv (from deg), pack fp16, store
#pragma unroll
    for (int mt = 0; mt < 2; mt++) {
        int r0 = row0 + wm * 32 + mt * 16 + g;
        int r1 = r0 + 8;
        float d0 = (r0 < NN) ? rsqrtf((float)(g_deg[r0] + 1)) : 0.f;
        float d1 = (r1 < NN) ? rsqrtf((float)(g_deg[r1] + 1)) : 0.f;
#pragma unroll
        for (int nt = 0; nt < 4; nt++) {
            int n = col0 + wn * 32 + nt * 8 + t2;
            if (r0 < NN) {
                __half2 p = __floats2half2_rn(acc[mt][nt][0] * d0, acc[mt][nt][1] * d0);
                *(__half2*)(g_gh + (size_t)r0 * 128 + n) = p;
            }
            if (r1 < NN) {
                __half2 p = __floats2half2_rn(acc[mt][nt][2] * d1, acc[mt][nt][3] * d1);
                *(__half2*)(g_gh + (size_t)r1 * 128 + n) = p;
            }
        }
    }
}

// ---------------- aggregation (gather CSR; writes split activations) --------
__global__ void __launch_bounds__(256) k_agg(const float* __restrict__ bias) {
    int n = (blockIdx.x * blockDim.x + threadIdx.x) >> 5;
    int lane = threadIdx.x & 31;
    if (n >= NN) return;
    const uint2* gb = (const uint2*)g_gh;       // 8B units; row stride = 32
    uint2 sv = gb[(size_t)n * 32 + lane];       // self-loop term
    __half2 h0 = *(__half2*)&sv.x, h1 = *(__half2*)&sv.y;
    float2 f0 = __half22float2(h0), f1 = __half22float2(h1);
    float4 acc = make_float4(f0.x, f0.y, f1.x, f1.y);

    int s = g_off[n], e = g_off[n + 1];
    for (int base = s; base < e; base += 32) {
        int cnt = e - base; if (cnt > 32) cnt = 32;
        int id = (lane < cnt) ? g_csr[base + lane] : 0;
        int jmax = cnt & ~1;
        for (int j = 0; j < jmax; j += 2) {
            int sa = __shfl_sync(0xffffffffu, id, j);
            int sb = __shfl_sync(0xffffffffu, id, j + 1);
            uint2 va = gb[(size_t)sa * 32 + lane];
            uint2 vb = gb[(size_t)sb * 32 + lane];
            __half2 s0 = __hadd2(*(__half2*)&va.x, *(__half2*)&vb.x);
            __half2 s1 = __hadd2(*(__half2*)&va.y, *(__half2*)&vb.y);
            float2 g0 = __half22float2(s0), g1 = __half22float2(s1);
            acc.x += g0.x; acc.y += g0.y; acc.z += g1.x; acc.w += g1.y;
        }
        if (cnt & 1) {
            int sa = __shfl_sync(0xffffffffu, id, cnt - 1);
            uint2 va = gb[(size_t)sa * 32 + lane];
            float2 g0 = __half22float2(*(__half2*)&va.x);
            float2 g1 = __half22float2(*(__half2*)&va.y);
            acc.x += g0.x; acc.y += g0.y; acc.z += g1.x; acc.w += g1.y;
        }
    }
    float dn = rsqrtf((float)(g_deg[n] + 1));
    float4 bb = *(const float4*)(bias + lane * 4);
    float4 o = make_float4(acc.x * dn + bb.x, acc.y * dn + bb.y,
                           acc.z * dn + bb.z, acc.w * dn + bb.w);
    uint2 hi, lo;
    split2(o.x, o.y, hi.x, lo.x);
    split2(o.z, o.w, hi.y, lo.y);
    *(uint2*)(g_ah + (size_t)n * 128 + lane * 4) = hi;
    *(uint2*)(g_al + (size_t)n * 128 + lane * 4) = lo;
}

// ---------------- mean pool per graph + output head -------------------------
__global__ void __launch_bounds__(128) k_pool(const int* __restrict__ batch,
                                              const float* __restrict__ Wout,
                                              const float* __restrict__ bout,
                                              float* __restrict__ out) {
    int gid = blockIdx.x;
    int c = threadIdx.x;
    int lo = 0, hi = NN;
    while (lo < hi) { int m = (lo + hi) >> 1; if (batch[m] < gid) lo = m + 1; else hi = m; }
    int start = lo;
    hi = NN;
    while (lo < hi) { int m = (lo + hi) >> 1; if (batch[m] < gid + 1) lo = m + 1; else hi = m; }
    int end = lo;

    float s = 0.f;
    for (int r = start; r < end; r++)
        s += __half2float(g_ah[(size_t)r * 128 + c]) +
             __half2float(g_al[(size_t)r * 128 + c]);
    __shared__ float pooled[128];
    int cnt = end - start;
    pooled[c] = (cnt > 0) ? s / (float)cnt : 0.f;
    __syncthreads();
    if (c < NOUT) {
        float a = bout[c];
#pragma unroll 8
        for (int k = 0; k < 128; k++) a += pooled[k] * Wout[k * NOUT + c];
        out[gid * NOUT + c] = a;
    }
}

// ---------------- launch ----------------------------------------------------
extern "C" void kernel_launch(void* const* d_in, const int* in_sizes, int n_in,
                              void* d_out, int out_size) {
    const float* x      = (const float*)d_in[0];
    const int*   ei     = (const int*)d_in[1];     // int32 (JAX x64 disabled)
    const int*   batch  = (const int*)d_in[2];     // int32
    const float* W_in   = (const float*)d_in[3];
    const float* b_in   = (const float*)d_in[4];
    const float* W_hid  = (const float*)d_in[5];
    const float* b_hid  = (const float*)d_in[6];
    const float* W_out  = (const float*)d_in[7];
    const float* b_out  = (const float*)d_in[8];
    float* out = (float*)d_out;

    cudaFuncSetAttribute(k_gemm_tc, cudaFuncAttributeMaxDynamicSharedMemorySize,
                         SMEM_BYTES);

    const int gemm_blocks = ((NN + 127) / 128) * 2;   // 128x64 tiles
    const int agg_blocks  = (NN * 32 + 255) / 256;

    // gemm0 kept as 4th launch (ncu capture slot)
    k_zero<<<(NN + 255) / 256, 256>>>();
    k_edge_prep<<<(NE / 4 + 255) / 256, 256>>>(ei);
    k_split<<<12500 + 64, 256>>>(x, W_in, W_hid);
    k_gemm_tc<<<gemm_blocks, 256, SMEM_BYTES>>>(0);          // <- profiled
    k_scan1<<<NB_SCAN, 1024>>>();
    k_scan2<<<1, 128>>>(NB_SCAN);
    k_scan3<<<(NN + 255) / 256, 256>>>();
    k_fill<<<(NE / 4 + 255) / 256, 256>>>(ei);

    k_agg<<<agg_blocks, 256>>>(b_in);
    for (int i = 0; i < 3; i++) {
        k_gemm_tc<<<gemm_blocks, 256, SMEM_BYTES>>>(i + 1);
        k_agg<<<agg_blocks, 256>>>(b_hid + (size_t)i * 128);
    }

    k_pool<<<NG, 128>>>(batch, W_out, b_out, out);
}